// round 17
// baseline (speedup 1.0000x reference)
#include <cuda_runtime.h>
#include <cuda_fp16.h>

#define B_SZ   16
#define NUM_CN 25000
#define NUM_VN 50000
#define NUM_E  200000
#define D_EMB  16
#define D_HID  32
#define D_MSG  16

typedef unsigned long long ULL;

// ---- scratch (device globals) ----
__device__ __half g_hf_x[(size_t)NUM_CN * B_SZ * D_HID];   // [CN][B][32] fp16
__device__ __half g_hf_z[(size_t)NUM_CN * B_SZ * D_HID];
__device__ __half g_hp[(size_t)2 * NUM_VN * B_SZ * D_HID]; // [pol][v*16+b][32] fp16
__device__ __half g_s[(size_t)2 * B_SZ * NUM_VN * D_HID];  // [pol][b][VN][32] fp16
__device__ __half g_W1t[32 * 80];                          // vn W1 transposed [n][k]
__device__ __half g_W2t[16 * 32];                          // vn W2 transposed [n][k]
__device__ int      g_cnt[4 * NUM_VN];                     // deg_x|deg_z|cur_x|cur_z
__device__ int      g_offs_x[NUM_VN + 1], g_offs_z[NUM_VN + 1];
__device__ unsigned g_csr_x[NUM_E],   g_csr_z[NUM_E];      // f | (mask<<16)
__device__ unsigned g_mask_x[NUM_CN], g_mask_z[NUM_CN];

// ---------------------------------------------------------------------------
// mma helpers (direct fragment loads; proven in R16)
__device__ __forceinline__ void mma16816(float* c, unsigned a0, unsigned a1,
                                         unsigned a2, unsigned a3,
                                         unsigned b0, unsigned b1) {
    asm volatile(
        "mma.sync.aligned.m16n8k16.row.col.f32.f16.f16.f32 "
        "{%0,%1,%2,%3}, {%4,%5,%6,%7}, {%8,%9}, {%0,%1,%2,%3};"
        : "+f"(c[0]), "+f"(c[1]), "+f"(c[2]), "+f"(c[3])
        : "r"(a0), "r"(a1), "r"(a2), "r"(a3), "r"(b0), "r"(b1));
}
__device__ __forceinline__ unsigned packh2(float x, float y) {
    __half2 h = __float22half2_rn(make_float2(x, y));
    return *reinterpret_cast<unsigned*>(&h);
}
__device__ __forceinline__ unsigned ldh2(const __half* p) {
    return *reinterpret_cast<const unsigned*>(p);
}

// ---------------------------------------------------------------------------
// kernel 1: TC partials (blocks < 18750) + prep hist/mask (blocks >= 18750)
// TC tile τ (one node x 16 batches): τ<25000 hf_x | <50000 hf_z | <100000 hp_x | else hp_z
// out[node*16+b][32] = h[b][node][0:16] @ W1seg[16x32]   (fp16 out)
#define PA_STRIDE 24
#define PW_STRIDE 24

__global__ void __launch_bounds__(256) partials_prep_kernel(
    const float* __restrict__ h_from_x, const float* __restrict__ h_from_z,
    const float* __restrict__ h_to,
    const float* __restrict__ Wx1, const float* __restrict__ Wz1,
    __half* __restrict__ hf_x, __half* __restrict__ hf_z, __half* __restrict__ hp,
    const int* __restrict__ to_x, const int* __restrict__ to_z,
    const int* __restrict__ syn_x, const int* __restrict__ syn_z,
    int* __restrict__ deg_x, int* __restrict__ deg_z,
    unsigned* __restrict__ mask_x, unsigned* __restrict__ mask_z)
{
    if (blockIdx.x >= 18750) {
        int i = (blockIdx.x - 18750) * 256 + threadIdx.x;
        if (i < NUM_E) {
            atomicAdd(&deg_x[__ldg(to_x + i)], 1);
            atomicAdd(&deg_z[__ldg(to_z + i)], 1);
        }
        if (i < NUM_CN) {
            unsigned mx = 0, mz = 0;
            #pragma unroll
            for (int b = 0; b < B_SZ; b++) {
                mx |= (unsigned)(__ldg(syn_x + (size_t)b * NUM_CN + i) & 1) << b;
                mz |= (unsigned)(__ldg(syn_z + (size_t)b * NUM_CN + i) & 1) << b;
            }
            mask_x[i] = mx;
            mask_z[i] = mz;
        }
        return;
    }

    // Wt[set][n][k]: set 0 = Wx1 rows 0..15, 1 = Wx1 rows 16..31, 2 = Wz1 lo, 3 = Wz1 hi
    __shared__ __align__(16) __half Wt[4][32 * PW_STRIDE];
    __shared__ __align__(16) __half As[8][16 * PA_STRIDE];

    int t = threadIdx.x;
    for (int i = t; i < 2048; i += 256) {
        int set = i >> 9;
        int n = (i >> 4) & 31;
        int k = i & 15;
        const float* W = (set >= 2) ? Wz1 : Wx1;
        int rowOff = (set & 1) ? 16 : 0;
        Wt[set][n * PW_STRIDE + k] = __float2half(W[(rowOff + k) * 32 + n]);
    }
    __syncthreads();

    int wid = t >> 5;
    int lane = t & 31;
    int tau = blockIdx.x * 8 + wid;    // 0..149999
    __half* A = &As[wid][0];

    const float* src;
    __half* dst;
    int node, N, set;
    if (tau < 25000)       { node = tau;          src = h_from_x; dst = hf_x; N = NUM_CN; set = 0; }
    else if (tau < 50000)  { node = tau - 25000;  src = h_from_z; dst = hf_z; N = NUM_CN; set = 2; }
    else if (tau < 100000) { node = tau - 50000;  src = h_to;     dst = hp;   N = NUM_VN; set = 1; }
    else                   { node = tau - 100000; src = h_to;
                             dst = hp + (size_t)NUM_VN * B_SZ * D_HID; N = NUM_VN; set = 3; }

    // stage A: row b = h[b][node][0:16] -> fp16
    {
        int r = lane >> 1, q = lane & 1;
        const float4* p = reinterpret_cast<const float4*>(
            src + ((size_t)r * N + node) * D_EMB) + q * 2;
        float4 f0 = __ldg(p), f1 = __ldg(p + 1);
        uint4 u;
        u.x = packh2(f0.x, f0.y);  u.y = packh2(f0.z, f0.w);
        u.z = packh2(f1.x, f1.y);  u.w = packh2(f1.z, f1.w);
        *reinterpret_cast<uint4*>(&A[r * PA_STRIDE + q * 8]) = u;
    }
    __syncwarp();

    int r = lane >> 2;
    int c = (lane & 3) * 2;
    int tt = lane & 3;
    const __half* W = &Wt[set][0];

    float cf[4][4];
    #pragma unroll
    for (int nn = 0; nn < 4; nn++)
        #pragma unroll
        for (int k = 0; k < 4; k++) cf[nn][k] = 0.f;

    unsigned a0 = ldh2(&A[r * PA_STRIDE + c]);
    unsigned a1 = ldh2(&A[(r + 8) * PA_STRIDE + c]);
    unsigned a2 = ldh2(&A[r * PA_STRIDE + c + 8]);
    unsigned a3 = ldh2(&A[(r + 8) * PA_STRIDE + c + 8]);
    #pragma unroll
    for (int nn = 0; nn < 4; nn++) {
        const __half* wrow = &W[(nn * 8 + r) * PW_STRIDE];
        unsigned b0 = ldh2(wrow + c);
        unsigned b1 = ldh2(wrow + c + 8);
        mma16816(cf[nn], a0, a1, a2, a3, b0, b1);
    }

    // store fp16: dst[(node*16 + row)*32 + nn*8 + tt*2]
    unsigned* d32 = reinterpret_cast<unsigned*>(dst);
    size_t base0 = ((size_t)node * 16 + r) * 16 + tt;        // u32 units
    size_t base1 = ((size_t)node * 16 + r + 8) * 16 + tt;
    #pragma unroll
    for (int nn = 0; nn < 4; nn++) {
        d32[base0 + nn * 4] = packh2(cf[nn][0], cf[nn][1]);
        d32[base1 + nn * 4] = packh2(cf[nn][2], cf[nn][3]);
    }
}

// ---------------------------------------------------------------------------
// kernel 2: exclusive scan (blocks 0,1) + vn TRANSPOSED fp16 weights (block 2)
__global__ void __launch_bounds__(1024) scan_kernel(
    const int* __restrict__ deg_x, const int* __restrict__ deg_z,
    int* __restrict__ offs_x, int* __restrict__ offs_z,
    const float* __restrict__ Wx2, const float* __restrict__ Wz2,
    const float* __restrict__ We1, const float* __restrict__ We2,
    __half* __restrict__ W1t, __half* __restrict__ W2t)
{
    if (blockIdx.x == 2) {
        int t = threadIdx.x;
        #pragma unroll
        for (int r = 0; r < 2; r++) {
            int el = r * 1024 + t;            // 0..2047 : Mx | Mz
            int pol = el >> 10;
            int i = (el >> 5) & 31;           // k within pol block
            int j = el & 31;                  // n
            const float* W2 = pol ? Wz2 : Wx2;
            const float* E1 = We1 + pol * 16 * 32;
            float sum = 0.f;
            #pragma unroll
            for (int k = 0; k < 16; k++)
                sum += W2[i * 16 + k] * E1[k * 32 + j];
            W1t[j * 80 + pol * 32 + i] = __float2half(sum);
        }
        if (t < 512) {
            int d = t >> 5, j = t & 31;       // We1 tail rows 32..47
            W1t[j * 80 + 64 + d] = __float2half(We1[(32 + d) * 32 + j]);
        } else {
            int idx = t - 512;                // We2 transpose: [16][32]
            int k = idx >> 4, n = idx & 15;
            W2t[n * 32 + k] = __float2half(We2[k * 16 + n]);
        }
        return;
    }

    const int* deg  = blockIdx.x == 0 ? deg_x  : deg_z;
    int*       offs = blockIdx.x == 0 ? offs_x : offs_z;

    __shared__ int wt[32];
    __shared__ int sbase;
    int t = threadIdx.x;
    int lane = t & 31, w = t >> 5;
    if (t == 0) sbase = 0;
    __syncthreads();

    for (int c = 0; c < NUM_VN; c += 1024) {
        int gid = c + t;
        int x = (gid < NUM_VN) ? deg[gid] : 0;
        #pragma unroll
        for (int o = 1; o < 32; o <<= 1) {
            int y = __shfl_up_sync(0xffffffffu, x, o);
            if (lane >= o) x += y;
        }
        if (lane == 31) wt[w] = x;
        __syncthreads();
        if (w == 0) {
            int y = wt[lane];
            #pragma unroll
            for (int o = 1; o < 32; o <<= 1) {
                int z = __shfl_up_sync(0xffffffffu, y, o);
                if (lane >= o) y += z;
            }
            wt[lane] = y;
        }
        __syncthreads();
        int incl = x + (w > 0 ? wt[w - 1] : 0) + sbase;
        if (gid < NUM_VN) offs[gid + 1] = incl;
        __syncthreads();
        if (t == 1023) sbase = incl;
        __syncthreads();
    }
    if (t == 0) offs[0] = 0;
}

// ---------------------------------------------------------------------------
// kernel 3: CSR fill
__global__ void __launch_bounds__(256) fill_kernel(
    const int* __restrict__ from_x, const int* __restrict__ to_x,
    const int* __restrict__ from_z, const int* __restrict__ to_z,
    const int* __restrict__ offs_x, const int* __restrict__ offs_z,
    const unsigned* __restrict__ mask_x, const unsigned* __restrict__ mask_z,
    int* __restrict__ cur_x, int* __restrict__ cur_z,
    unsigned* __restrict__ csr_x, unsigned* __restrict__ csr_z)
{
    int e = blockIdx.x * 256 + threadIdx.x;
    if (e >= NUM_E) return;
    {
        int v = __ldg(to_x + e);
        int f = __ldg(from_x + e);
        int p = atomicAdd(&cur_x[v], 1);
        csr_x[__ldg(offs_x + v) + p] = (unsigned)f | (__ldg(mask_x + f) << 16);
    }
    {
        int v = __ldg(to_z + e);
        int f = __ldg(from_z + e);
        int p = atomicAdd(&cur_z[v], 1);
        csr_z[__ldg(offs_z + v) + p] = (unsigned)f | (__ldg(mask_z + f) << 16);
    }
}

// ---------------------------------------------------------------------------
// kernel 4 (PROFILED SLOT): msg kernel — R10 structure, hp precomputed.
// No smem, no syncthreads: warp = one v; lane = b_hi*8 + chunk.
__global__ void __launch_bounds__(256) msg_kernel(
    const __half* __restrict__ hfx, const __half* __restrict__ hfz,
    const __half* __restrict__ hp,
    const int* __restrict__ offs_x, const unsigned* __restrict__ csr_x,
    const int* __restrict__ offs_z, const unsigned* __restrict__ csr_z,
    __half* __restrict__ s_out)
{
    int pol = blockIdx.y;
    const uint2*    hf2  = reinterpret_cast<const uint2*>(pol ? hfz : hfx);
    const uint2*    hp2  = reinterpret_cast<const uint2*>(hp) +
                           (size_t)pol * NUM_VN * B_SZ * 8;
    const int*      offs = pol ? offs_z : offs_x;
    const unsigned* csr  = pol ? csr_z  : csr_x;

    int t = threadIdx.x;
    int wid = t >> 5;
    int lane = t & 31;
    int v = blockIdx.x * 8 + wid;             // grid.x=6250 -> v in [0,50000)
    int b_hi = (lane >> 3) & 3;
    int chunk = lane & 7;

    // load precomputed hp for the lane's 4 b-groups (fp16 -> fp32)
    float2 hpa[4], hpb[4];
    #pragma unroll
    for (int bg = 0; bg < 4; bg++) {
        int b = bg * 4 + b_hi;
        uint2 u = __ldg(hp2 + ((size_t)v * B_SZ + b) * 8 + chunk);
        hpa[bg] = __half22float2(*reinterpret_cast<__half2*>(&u.x));
        hpb[bg] = __half22float2(*reinterpret_cast<__half2*>(&u.y));
    }

    float s0[4] = {0,0,0,0}, s1[4] = {0,0,0,0};
    float s2[4] = {0,0,0,0}, s3[4] = {0,0,0,0};

    int beg = __ldg(offs + v), end = __ldg(offs + v + 1);
    unsigned shift0 = 16 + b_hi;
    unsigned lane_off = (unsigned)(b_hi * 8 + chunk);

    for (int e = beg; e < end; e += 2) {
        unsigned pka = __ldg(csr + e);
        unsigned pkb = (e + 1 < end) ? __ldg(csr + e + 1) : 0u;

        unsigned basea = (pka & 0xFFFFu) * 128u + lane_off;
        unsigned baseb = (pkb & 0xFFFFu) * 128u + lane_off;

        uint2 va[4], vb[4];
        bool ga[4], gb[4];
        #pragma unroll
        for (int bg = 0; bg < 4; bg++) {
            ga[bg] = (pka >> (shift0 + bg * 4)) & 1u;
            gb[bg] = (pkb >> (shift0 + bg * 4)) & 1u;
            if (ga[bg]) va[bg] = __ldg(hf2 + basea + bg * 32u);
            if (gb[bg]) vb[bg] = __ldg(hf2 + baseb + bg * 32u);
        }
        #pragma unroll
        for (int bg = 0; bg < 4; bg++) {
            if (ga[bg]) {
                float2 lo = __half22float2(*reinterpret_cast<__half2*>(&va[bg].x));
                float2 hi = __half22float2(*reinterpret_cast<__half2*>(&va[bg].y));
                s0[bg] += fmaxf(lo.x + hpa[bg].x, 0.f);
                s1[bg] += fmaxf(lo.y + hpa[bg].y, 0.f);
                s2[bg] += fmaxf(hi.x + hpb[bg].x, 0.f);
                s3[bg] += fmaxf(hi.y + hpb[bg].y, 0.f);
            }
            if (gb[bg]) {
                float2 lo = __half22float2(*reinterpret_cast<__half2*>(&vb[bg].x));
                float2 hi = __half22float2(*reinterpret_cast<__half2*>(&vb[bg].y));
                s0[bg] += fmaxf(lo.x + hpa[bg].x, 0.f);
                s1[bg] += fmaxf(lo.y + hpa[bg].y, 0.f);
                s2[bg] += fmaxf(hi.x + hpb[bg].x, 0.f);
                s3[bg] += fmaxf(hi.y + hpb[bg].y, 0.f);
            }
        }
    }

    #pragma unroll
    for (int bg = 0; bg < 4; bg++) {
        int b = bg * 4 + b_hi;
        uint2 st;
        st.x = packh2(s0[bg], s1[bg]);
        st.y = packh2(s2[bg], s3[bg]);
        reinterpret_cast<uint2*>(s_out)[
            (((size_t)pol * B_SZ + b) * NUM_VN + v) * 8 + chunk] = st;
    }
}

// ---------------------------------------------------------------------------
// kernel 5: vn kernel — HMMA with direct fragment loads (proven R16).
#define A_STRIDE 88
#define W_STRIDE 88

__global__ void __launch_bounds__(256) vn_kernel(
    const __half* __restrict__ s, const float* __restrict__ h_to,
    const __half* __restrict__ W1t, const __half* __restrict__ W2t,
    float* __restrict__ out)
{
    __shared__ __align__(16) __half W1s[32 * W_STRIDE];
    __shared__ __align__(16) __half W2s[16 * W_STRIDE];
    __shared__ __align__(16) __half As[8][16 * A_STRIDE];

    int t = threadIdx.x;
    for (int i = t; i < 320; i += 256) {
        int r = i / 10, q = i - r * 10;
        *reinterpret_cast<uint4*>(&W1s[r * W_STRIDE + q * 8]) =
            reinterpret_cast<const uint4*>(W1t)[i];
    }
    for (int i = t; i < 64; i += 256) {
        int r = i >> 2, q = i & 3;
        *reinterpret_cast<uint4*>(&W2s[r * W_STRIDE + q * 8]) =
            reinterpret_cast<const uint4*>(W2t)[i];
    }
    __syncthreads();

    int wid = t >> 5;
    int lane = t & 31;
    int tile = blockIdx.x * 8 + wid;            // 50000 tiles total
    int rbase = tile * 16;
    __half* A = &As[wid][0];
    const size_t BVN = (size_t)B_SZ * NUM_VN;

    {
        const uint4* px = reinterpret_cast<const uint4*>(s) + (size_t)rbase * 4;
        const uint4* pz = reinterpret_cast<const uint4*>(s) + (BVN + rbase) * 4;
        #pragma unroll
        for (int i = lane; i < 64; i += 32) {
            int r = i >> 2, q = i & 3;
            *reinterpret_cast<uint4*>(&A[r * A_STRIDE + q * 8])      = __ldg(px + i);
            *reinterpret_cast<uint4*>(&A[r * A_STRIDE + 32 + q * 8]) = __ldg(pz + i);
        }
        const float4* ph = reinterpret_cast<const float4*>(h_to + (size_t)rbase * D_EMB);
        #pragma unroll
        for (int i = lane; i < 64; i += 32) {
            int r = i >> 2, q = i & 3;
            float4 v = __ldg(ph + i);
            uint2 u;
            u.x = packh2(v.x, v.y);
            u.y = packh2(v.z, v.w);
            *reinterpret_cast<uint2*>(&A[r * A_STRIDE + 64 + q * 4]) = u;
        }
    }
    __syncwarp();

    int r = lane >> 2;
    int c = (lane & 3) * 2;

    float cf[4][4];
    #pragma unroll
    for (int nn = 0; nn < 4; nn++)
        #pragma unroll
        for (int k = 0; k < 4; k++) cf[nn][k] = 0.f;

    #pragma unroll
    for (int kk = 0; kk < 5; kk++) {
        int ka = kk * 16 + c;
        unsigned a0 = ldh2(&A[r * A_STRIDE + ka]);
        unsigned a1 = ldh2(&A[(r + 8) * A_STRIDE + ka]);
        unsigned a2 = ldh2(&A[r * A_STRIDE + ka + 8]);
        unsigned a3 = ldh2(&A[(r + 8) * A_STRIDE + ka + 8]);
        #pragma unroll
        for (int nn = 0; nn < 4; nn++) {
            const __half* wrow = &W1s[(nn * 8 + r) * W_STRIDE + ka];
            unsigned b0 = ldh2(wrow);
            unsigned b1 = ldh2(wrow + 8);
            mma16816(cf[nn], a0, a1, a2, a3, b0, b1);
        }
    }

    float d[2][4];
    #pragma unroll
    for (int nn = 0; nn < 2; nn++)
        #pragma unroll
        for (int k = 0; k < 4; k++) d[nn][k] = 0.f;

    #pragma unroll
    for (int kk2 = 0; kk2 < 2; kk2++) {
        int lo = kk2 * 2, hi = kk2 * 2 + 1;
        unsigned a0 = packh2(fmaxf(cf[lo][0], 0.f), fmaxf(cf[lo][1], 0.f));
        unsigned a1 = packh2(fmaxf(cf[lo][2], 0.f), fmaxf(cf[lo][3], 0.f));
        unsigned a2 = packh2(fmaxf(cf[hi][0], 0.f), fmaxf(cf[hi][1], 0.f));
        unsigned a3 = packh2(fmaxf(cf[hi][2], 0.f), fmaxf(cf[hi][3], 0.f));
        int ka = kk2 * 16 + c;
        #pragma unroll
        for (int nn = 0; nn < 2; nn++) {
            const __half* wrow = &W2s[(nn * 8 + r) * W_STRIDE + ka];
            unsigned b0 = ldh2(wrow);
            unsigned b1 = ldh2(wrow + 8);
            mma16816(d[nn], a0, a1, a2, a3, b0, b1);
        }
    }

    int tt = lane & 3;
    #pragma unroll
    for (int nn = 0; nn < 2; nn++) {
        float2 lo = make_float2(d[nn][0], d[nn][1]);
        float2 hi = make_float2(d[nn][2], d[nn][3]);
        *reinterpret_cast<float2*>(out + ((size_t)rbase + r)     * 16 + nn * 8 + tt * 2) = lo;
        *reinterpret_cast<float2*>(out + ((size_t)rbase + r + 8) * 16 + nn * 8 + tt * 2) = hi;
    }
}

// ---------------------------------------------------------------------------
extern "C" void kernel_launch(void* const* d_in, const int* in_sizes, int n_in,
                              void* d_out, int out_size) {
    const float* h_from_x   = (const float*)d_in[0];
    const float* h_from_z   = (const float*)d_in[1];
    const float* h_to       = (const float*)d_in[2];
    const int*   syndrome_x = (const int*)d_in[3];
    const int*   syndrome_z = (const int*)d_in[4];
    const int*   from_ind_x = (const int*)d_in[5];
    const int*   to_ind_x   = (const int*)d_in[6];
    const int*   from_ind_z = (const int*)d_in[7];
    const int*   to_ind_z   = (const int*)d_in[8];
    const float* Wx1        = (const float*)d_in[9];
    const float* Wx2        = (const float*)d_in[10];
    const float* Wz1        = (const float*)d_in[11];
    const float* Wz2        = (const float*)d_in[12];
    const float* We1        = (const float*)d_in[13];
    const float* We2        = (const float*)d_in[14];
    float* out = (float*)d_out;

    __half *hf_x, *hf_z, *hp, *s, *W1t, *W2t;
    int *cnt, *offs_x, *offs_z;
    unsigned *csr_x, *csr_z, *mask_x, *mask_z;
    cudaGetSymbolAddress((void**)&hf_x, g_hf_x);
    cudaGetSymbolAddress((void**)&hf_z, g_hf_z);
    cudaGetSymbolAddress((void**)&hp,   g_hp);
    cudaGetSymbolAddress((void**)&s,    g_s);
    cudaGetSymbolAddress((void**)&W1t,  g_W1t);
    cudaGetSymbolAddress((void**)&W2t,  g_W2t);
    cudaGetSymbolAddress((void**)&cnt,  g_cnt);
    cudaGetSymbolAddress((void**)&offs_x, g_offs_x);
    cudaGetSymbolAddress((void**)&offs_z, g_offs_z);
    cudaGetSymbolAddress((void**)&csr_x, g_csr_x);
    cudaGetSymbolAddress((void**)&csr_z, g_csr_z);
    cudaGetSymbolAddress((void**)&mask_x, g_mask_x);
    cudaGetSymbolAddress((void**)&mask_z, g_mask_z);

    int *deg_x = cnt, *deg_z = cnt + NUM_VN;
    int *cur_x = cnt + 2 * NUM_VN, *cur_z = cnt + 3 * NUM_VN;

    cudaMemsetAsync(cnt, 0, 4 * NUM_VN * sizeof(int), 0);

    // k1: TC partials (hf_x, hf_z, hp_x, hp_z) + hist/mask blocks
    partials_prep_kernel<<<18750 + (NUM_E + 255) / 256, 256>>>(
        h_from_x, h_from_z, h_to, Wx1, Wz1, hf_x, hf_z, hp,
        to_ind_x, to_ind_z, syndrome_x, syndrome_z,
        deg_x, deg_z, mask_x, mask_z);

    // k2: scan (blocks 0,1) + vn transposed fp16 weights (block 2)
    scan_kernel<<<3, 1024>>>(deg_x, deg_z, offs_x, offs_z,
                             Wx2, Wz2, We1, We2, W1t, W2t);

    // k3: CSR fill
    fill_kernel<<<(NUM_E + 255) / 256, 256>>>(
        from_ind_x, to_ind_x, from_ind_z, to_ind_z,
        offs_x, offs_z, mask_x, mask_z, cur_x, cur_z, csr_x, csr_z);

    // k4 (profiled slot): messages — hp precomputed, no smem
    msg_kernel<<<dim3(6250, 2), 256>>>(
        hf_x, hf_z, hp,
        offs_x, csr_x, offs_z, csr_z, s);

    // k5: vertex MLP — HMMA
    vn_kernel<<<6250, 256>>>(s, h_to, W1t, W2t, out);
}